// round 1
// baseline (speedup 1.0000x reference)
#include <cuda_runtime.h>
#include <math.h>

// Problem constants (fixed by the reference)
#define BSZ  4096      // batch
#define HDIM 1024      // hidden
#define TLEN 128       // forecast steps
#define JT   (HDIM/32) // 32 j-tiles along hidden dim

// Persistent state (ping-pong) — __device__ globals, no runtime allocation.
__device__ float g_h[2][(size_t)BSZ * HDIM];
__device__ float g_c[2][(size_t)BSZ * HDIM];
__device__ float g_partial[(size_t)BSZ * JT];
__device__ float g_pred[BSZ];

__device__ __forceinline__ float sigmoidf_(float x) {
    return 1.0f / (1.0f + __expf(-x));
}

// Fused LSTM step:
//   gates[b, g*H+j] = sum_k h_in[b,k] * W_hh[g*H+j, k]  (+ x_b*W_ih + bias in epilogue)
// Tile: 128 batch rows x 32 j-columns (=> 128 gate columns, 4 gates x 32 j).
// Thread cols chosen so one thread owns all 4 gates of its j values -> pointwise
// LSTM update is register-local, no cross-thread exchange needed.
__global__ __launch_bounds__(256) void lstm_step(
    const float* __restrict__ h_in, const float* __restrict__ c_in,
    float* __restrict__ h_out, float* __restrict__ c_out,
    const float* __restrict__ xprev, int use_x,
    const float* __restrict__ W_ih, const float* __restrict__ W_hh,
    const float* __restrict__ b_ih, const float* __restrict__ b_hh,
    const float* __restrict__ W_out, float* __restrict__ partial)
{
    __shared__ float As[128 * 9];  // h tile   [row=b][k], pad 9 to kill bank conflicts
    __shared__ float Bs[128 * 9];  // W tile   [row=col][k]

    const int b0  = blockIdx.x * 128;
    const int j0  = blockIdx.y * 32;
    const int tid = threadIdx.x;
    const int tx  = tid & 15;   // 0..15
    const int ty  = tid >> 4;   // 0..15

    float acc[8][8];
#pragma unroll
    for (int r = 0; r < 8; r++)
#pragma unroll
        for (int c = 0; c < 8; c++) acc[r][c] = 0.0f;

    // Global load assignment: 128 rows x 8 k per buffer; 256 threads do one
    // float4 each.
    const int ldrow = tid >> 1;          // 0..127
    const int ldk   = (tid & 1) * 4;     // 0 or 4

    const float* Ag = h_in + (size_t)(b0 + ldrow) * HDIM + ldk;
    const int wrow  = (ldrow >> 5) * HDIM + j0 + (ldrow & 31);  // gate*H + j
    const float* Bg = W_hh + (size_t)wrow * HDIM + ldk;

    for (int k0 = 0; k0 < HDIM; k0 += 8) {
        // Prefetch into registers before the sync (overlaps previous compute)
        float4 av = *(const float4*)(Ag + k0);
        float4 bv = *(const float4*)(Bg + k0);
        __syncthreads();
        As[ldrow * 9 + ldk + 0] = av.x;
        As[ldrow * 9 + ldk + 1] = av.y;
        As[ldrow * 9 + ldk + 2] = av.z;
        As[ldrow * 9 + ldk + 3] = av.w;
        Bs[ldrow * 9 + ldk + 0] = bv.x;
        Bs[ldrow * 9 + ldk + 1] = bv.y;
        Bs[ldrow * 9 + ldk + 2] = bv.z;
        Bs[ldrow * 9 + ldk + 3] = bv.w;
        __syncthreads();

#pragma unroll
        for (int kk = 0; kk < 8; kk++) {
            float a[8], bb[8];
#pragma unroll
            for (int rr = 0; rr < 8; rr++)
                a[rr] = As[(ty * 8 + rr) * 9 + kk];
#pragma unroll
            for (int cc = 0; cc < 8; cc++) {
                int g  = cc >> 1;
                int jl = cc & 1;
                bb[cc] = Bs[(g * 32 + tx * 2 + jl) * 9 + kk];
            }
#pragma unroll
            for (int rr = 0; rr < 8; rr++)
#pragma unroll
                for (int cc = 0; cc < 8; cc++)
                    acc[rr][cc] = fmaf(a[rr], bb[cc], acc[rr][cc]);
        }
    }

    // Epilogue: fold in x*W_ih + (b_ih+b_hh), run LSTM pointwise, emit pred partials.
    float wih[8], bias[8];
#pragma unroll
    for (int cc = 0; cc < 8; cc++) {
        int g  = cc >> 1;
        int jl = cc & 1;
        int r  = g * HDIM + j0 + tx * 2 + jl;
        wih[cc]  = W_ih[r];
        bias[cc] = b_ih[r] + b_hh[r];
    }
    float wout0 = W_out[j0 + tx * 2 + 0];
    float wout1 = W_out[j0 + tx * 2 + 1];

    float psum[8];
#pragma unroll
    for (int rr = 0; rr < 8; rr++) {
        const int b = b0 + ty * 8 + rr;
        const float xb = use_x ? xprev[b] : 0.0f;
        float p = 0.0f;
#pragma unroll
        for (int jl = 0; jl < 2; jl++) {
            const float iv = acc[rr][0 + jl] + xb * wih[0 + jl] + bias[0 + jl];
            const float fv = acc[rr][2 + jl] + xb * wih[2 + jl] + bias[2 + jl];
            const float gv = acc[rr][4 + jl] + xb * wih[4 + jl] + bias[4 + jl];
            const float ov = acc[rr][6 + jl] + xb * wih[6 + jl] + bias[6 + jl];
            const int j = j0 + tx * 2 + jl;
            const size_t idx = (size_t)b * HDIM + j;
            const float cold = c_in[idx];
            const float cnew = sigmoidf_(fv) * cold + sigmoidf_(iv) * tanhf(gv);
            const float hnew = sigmoidf_(ov) * tanhf(cnew);
            c_out[idx] = cnew;
            h_out[idx] = hnew;
            p = fmaf(hnew, (jl == 0) ? wout0 : wout1, p);
        }
        psum[rr] = p;
    }

    // Reduce pred partials across the 16 tx lanes (each half-warp = one ty).
    // Fixed order -> deterministic.
#pragma unroll
    for (int rr = 0; rr < 8; rr++) {
        float p = psum[rr];
        p += __shfl_xor_sync(0xffffffffu, p, 1);
        p += __shfl_xor_sync(0xffffffffu, p, 2);
        p += __shfl_xor_sync(0xffffffffu, p, 4);
        p += __shfl_xor_sync(0xffffffffu, p, 8);
        if (tx == 0)
            partial[(size_t)(b0 + ty * 8 + rr) * JT + blockIdx.y] = p;
    }
}

// pred[b] = sum_jt partial[b][jt] + b_out; also writes the output column t.
__global__ void pred_reduce(const float* __restrict__ partial,
                            const float* __restrict__ b_out,
                            float* __restrict__ pred,
                            float* __restrict__ out, int t)
{
    const int b = blockIdx.x * blockDim.x + threadIdx.x;
    if (b < BSZ) {
        float s = b_out[0];
        const float* p = partial + (size_t)b * JT;
#pragma unroll
        for (int jt = 0; jt < JT; jt++) s += p[jt];
        pred[b] = s;
        out[(size_t)b * TLEN + t] = s;
    }
}

extern "C" void kernel_launch(void* const* d_in, const int* in_sizes, int n_in,
                              void* d_out, int out_size)
{
    const float* hidden = (const float*)d_in[0];
    const float* cell   = (const float*)d_in[1];
    const float* W_ih   = (const float*)d_in[2];
    const float* W_hh   = (const float*)d_in[3];
    const float* b_ih   = (const float*)d_in[4];
    const float* b_hh   = (const float*)d_in[5];
    const float* W_out  = (const float*)d_in[6];
    const float* b_out  = (const float*)d_in[7];
    float* out = (float*)d_out;

    float *hbuf, *cbuf, *part, *pred;
    cudaGetSymbolAddress((void**)&hbuf, g_h);
    cudaGetSymbolAddress((void**)&cbuf, g_c);
    cudaGetSymbolAddress((void**)&part, g_partial);
    cudaGetSymbolAddress((void**)&pred, g_pred);

    const size_t NB = (size_t)BSZ * HDIM;
    dim3 grid(BSZ / 128, HDIM / 32);

    for (int t = 0; t < TLEN; t++) {
        const int so = t & 1;                 // output slot
        float* h_o = hbuf + (size_t)so * NB;
        float* c_o = cbuf + (size_t)so * NB;
        const float* h_i = (t == 0) ? hidden : hbuf + (size_t)(so ^ 1) * NB;
        const float* c_i = (t == 0) ? cell   : cbuf + (size_t)(so ^ 1) * NB;

        lstm_step<<<grid, 256>>>(h_i, c_i, h_o, c_o,
                                 pred, (t > 0) ? 1 : 0,
                                 W_ih, W_hh, b_ih, b_hh, W_out, part);
        pred_reduce<<<BSZ / 256, 256>>>(part, b_out, pred, out, t);
    }
}

// round 3
// speedup vs baseline: 11.4605x; 11.4605x over previous
#include <cuda_runtime.h>
#include <cuda_bf16.h>
#include <math.h>
#include <stdint.h>

// ---------------- problem constants ----------------
#define HDIM  1024
#define BSZ   4096
#define TLEN  128
#define K3    3072            // split-bf16 packed K: [h_hi | h_lo | h_hi]
#define NGATE 4096            // 4 gates x HDIM, interleaved n' = j*4 + g
#define MT    256             // M tile
#define NT    256             // N tile (= 64 j's x 4 gates)
#define KC    64              // K chunk (bf16) = 128B rows, SW128 atom
#define NCHUNK (K3/KC)        // 48
#define NSTAGE 3
#define JT    16              // pred partial tiles per batch row

// tcgen05 is an arch-specific feature: it may only appear in the compute_103a /
// compute_100a PTX passes. The harness also emits a plain compute_103 pass,
// which must not see the asm.
#if defined(__CUDA_ARCH__) && (defined(__CUDA_ARCH_FEAT_SM103_ALL) || defined(__CUDA_ARCH_FEAT_SM100_ALL) || defined(__CUDA_ARCH_FEAT_SM101_ALL))
#define HAS_TCGEN05 1
#else
#define HAS_TCGEN05 0
#endif

// ---------------- persistent device state ----------------
__device__ __nv_bfloat16 g_A[2][(size_t)BSZ * K3];     // activations, split-packed (ping-pong)
__device__ __nv_bfloat16 g_Bp[(size_t)NGATE * K3];     // weights, split-packed + gate-interleaved
__device__ float g_c[(size_t)BSZ * HDIM];              // cell state (in-place)
__device__ float g_biasp[NGATE];                       // b_ih+b_hh, interleaved
__device__ float g_wihp[NGATE];                        // W_ih col 0, interleaved
__device__ float g_woutp[HDIM];
__device__ float g_partial[(size_t)BSZ * JT];
__device__ float g_pred[BSZ];

// ---------------- smem layout (dynamic) ----------------
#define SM_TMEM   0
#define SM_FULL0  64                         // 3 x 8B
#define SM_EMPTY0 (SM_FULL0 + 8*NSTAGE)      // 3 x 8B
#define SM_DONE   (SM_EMPTY0 + 8*NSTAGE)
#define SM_STAGE  1024
#define STAGE_BYTES 65536                    // A 32KB + B 32KB
#define SM_A_OFF  0
#define SM_B_OFF  32768
#define DSMEM (SM_STAGE + NSTAGE*STAGE_BYTES)

#define N_PROD_THREADS 128                   // warps 1..4

// idesc: F32 accum, BF16 a/b, N=256, M=128
#define MMA_IDESC 0x08400490u

// ---------------- arch-neutral PTX helpers ----------------
__device__ __forceinline__ uint32_t smem_u32(const void* p) {
    uint32_t a;
    asm("{ .reg .u64 t; cvta.to.shared.u64 t, %1; cvt.u32.u64 %0, t; }" : "=r"(a) : "l"(p));
    return a;
}
__device__ __forceinline__ uint32_t elect1() {
    uint32_t r;
    asm volatile("{ .reg .pred p; elect.sync _|p, 0xFFFFFFFF; selp.b32 %0, 1, 0, p; }" : "=r"(r));
    return r;
}
#define MBARRIER_INIT(addr, cnt) \
    asm volatile("mbarrier.init.shared.b64 [%0], %1;" :: "r"((uint32_t)(addr)), "r"((uint32_t)(cnt)) : "memory")
#define MBARRIER_WAIT_PARITY(addr, par) do { \
    uint32_t _m = (uint32_t)(addr); uint32_t _p = (uint32_t)(par); uint32_t _d; \
    asm volatile("{ .reg .pred p; mbarrier.try_wait.parity.acquire.cta.shared::cta.b64 p, [%1], %2; selp.b32 %0,1,0,p; }" \
        : "=r"(_d) : "r"(_m), "r"(_p) : "memory"); \
    if (!_d) { \
        asm volatile("{ .reg .pred P1; WL_%=: mbarrier.try_wait.parity.acquire.cta.shared::cta.b64 P1, [%0], %1, 0x989680; @P1 bra.uni WD_%=; bra.uni WL_%=; WD_%=: }" \
            :: "r"(_m), "r"(_p) : "memory"); \
    } } while (0)
__device__ __forceinline__ void cp16(uint32_t saddr, const void* gaddr) {
    asm volatile("cp.async.cg.shared.global [%0], [%1], 16;" :: "r"(saddr), "l"(gaddr));
}
__device__ __forceinline__ void cp_arrive(uint32_t mbar) {
    asm volatile("cp.async.mbarrier.arrive.noinc.shared::cta.b64 [%0];" :: "r"(mbar) : "memory");
}
__device__ __forceinline__ uint32_t swz128(uint32_t o) { return o ^ ((o >> 3) & 0x70); }

// SW128 K-major smem descriptor (layout 2, version 1, SBO=64, LBO=1)
static __device__ __forceinline__ uint64_t make_desc_sw128(uint32_t addr) {
    const uint64_t base = (uint64_t(2) << 61) | (uint64_t(1) << 46) | (uint64_t(64) << 32) | (uint64_t(1) << 16);
    return base | ((uint64_t)(addr >> 4) & 0x3FFF);
}

// ---------------- tcgen05 helpers (sm_103a-only pass) ----------------
#if HAS_TCGEN05
#define TCGEN05_ALLOC(sa, n) \
    asm volatile("tcgen05.alloc.cta_group::1.sync.aligned.shared::cta.b32 [%0], %1;" :: "r"((uint32_t)(sa)), "r"((uint32_t)(n)) : "memory")
#define TCGEN05_DEALLOC(t, n) \
    asm volatile("tcgen05.dealloc.cta_group::1.sync.aligned.b32 %0, %1;" :: "r"(t), "r"((uint32_t)(n)))
#define TCGEN05_RELINQUISH() \
    asm volatile("tcgen05.relinquish_alloc_permit.cta_group::1.sync.aligned;")
#define TCGEN05_COMMIT(mb) \
    asm volatile("tcgen05.commit.cta_group::1.mbarrier::arrive::one.shared::cluster.b64 [%0];" :: "r"((uint32_t)(mb)) : "memory")
#define TCGEN05_FENCE_AFTER()  asm volatile("tcgen05.fence::after_thread_sync;" ::: "memory")
#define TCGEN05_WAIT_LD()      asm volatile("tcgen05.wait::ld.sync.aligned;" ::: "memory")
#define FENCE_PROXY_ASYNC()    asm volatile("fence.proxy.async.shared::cta;" ::: "memory")

#define TCGEN05_LD_X32(r, ta) \
    asm volatile("tcgen05.ld.sync.aligned.32x32b.x32.b32 " \
        "{%0,%1,%2,%3,%4,%5,%6,%7,%8,%9,%10,%11,%12,%13,%14,%15," \
        "%16,%17,%18,%19,%20,%21,%22,%23,%24,%25,%26,%27,%28,%29,%30,%31}, [%32];" \
        : "=r"((r)[0]),"=r"((r)[1]),"=r"((r)[2]),"=r"((r)[3]),"=r"((r)[4]),"=r"((r)[5]),"=r"((r)[6]),"=r"((r)[7]), \
          "=r"((r)[8]),"=r"((r)[9]),"=r"((r)[10]),"=r"((r)[11]),"=r"((r)[12]),"=r"((r)[13]),"=r"((r)[14]),"=r"((r)[15]), \
          "=r"((r)[16]),"=r"((r)[17]),"=r"((r)[18]),"=r"((r)[19]),"=r"((r)[20]),"=r"((r)[21]),"=r"((r)[22]),"=r"((r)[23]), \
          "=r"((r)[24]),"=r"((r)[25]),"=r"((r)[26]),"=r"((r)[27]),"=r"((r)[28]),"=r"((r)[29]),"=r"((r)[30]),"=r"((r)[31]) \
        : "r"(ta))

__device__ __forceinline__ void mma_f16_ss(uint32_t d, uint64_t ad, uint64_t bd, uint32_t en) {
    asm volatile(
        "{ .reg .pred p; setp.ne.u32 p, %4, 0;\n\t"
        "tcgen05.mma.cta_group::1.kind::f16 [%0], %1, %2, %3, {%5,%5,%5,%5}, p; }"
        :: "r"(d), "l"(ad), "l"(bd), "r"(MMA_IDESC), "r"(en), "r"(0u) : "memory");
}
#endif  // HAS_TCGEN05

// ---------------- prep kernels ----------------
__global__ void prep_weights(const float* __restrict__ W_ih, const float* __restrict__ W_hh,
                             const float* __restrict__ b_ih, const float* __restrict__ b_hh,
                             const float* __restrict__ W_out,
                             __nv_bfloat16* __restrict__ Bp, float* __restrict__ biasp,
                             float* __restrict__ wihp, float* __restrict__ woutp)
{
    int idx = blockIdx.x * blockDim.x + threadIdx.x;
    if (idx >= NGATE * HDIM) return;
    int np = idx / HDIM, k = idx - np * HDIM;
    int gg = np & 3, j = np >> 2;
    int src = gg * HDIM + j;
    float w = W_hh[(size_t)src * HDIM + k];
    __nv_bfloat16 hi = __float2bfloat16_rn(w);
    __nv_bfloat16 lo = __float2bfloat16_rn(w - __bfloat162float(hi));
    Bp[(size_t)np * K3 + k]        = hi;
    Bp[(size_t)np * K3 + 1024 + k] = hi;
    Bp[(size_t)np * K3 + 2048 + k] = lo;
    if (k == 0) { biasp[np] = b_ih[src] + b_hh[src]; wihp[np] = W_ih[src]; }
    if (np == 0) woutp[k] = W_out[k];
}

__global__ void prep_state(const float* __restrict__ hidden, const float* __restrict__ cell,
                           __nv_bfloat16* __restrict__ A0, float* __restrict__ cbuf)
{
    int idx = blockIdx.x * blockDim.x + threadIdx.x;
    if (idx >= BSZ * HDIM) return;
    int m = idx / HDIM, k = idx - m * HDIM;
    float h = hidden[idx];
    __nv_bfloat16 hi = __float2bfloat16_rn(h);
    __nv_bfloat16 lo = __float2bfloat16_rn(h - __bfloat162float(hi));
    A0[(size_t)m * K3 + k]        = hi;
    A0[(size_t)m * K3 + 1024 + k] = lo;
    A0[(size_t)m * K3 + 2048 + k] = hi;
    cbuf[idx] = cell[idx];
}

// ---------------- fused LSTM step (tcgen05) ----------------
__global__ void __launch_bounds__(256, 1)
lstm_step_mma(const __nv_bfloat16* __restrict__ Ain, __nv_bfloat16* __restrict__ Aout,
              const __nv_bfloat16* __restrict__ Bp, float* __restrict__ cbuf,
              const float* __restrict__ biasp, const float* __restrict__ wihp,
              const float* __restrict__ woutp, const float* __restrict__ pred,
              int use_x, float* __restrict__ partial)
{
#if HAS_TCGEN05
    extern __shared__ char smem[];
    const uint32_t sbase = smem_u32(smem);
    const int tid = threadIdx.x, wid = tid >> 5, lid = tid & 31;
    const int m0 = blockIdx.x * MT, n0 = blockIdx.y * NT, j0 = n0 >> 2;

    if (tid == 0) {
#pragma unroll
        for (int s = 0; s < NSTAGE; s++) {
            MBARRIER_INIT(sbase + SM_FULL0 + 8 * s, N_PROD_THREADS);
            MBARRIER_INIT(sbase + SM_EMPTY0 + 8 * s, 1);
        }
        MBARRIER_INIT(sbase + SM_DONE, 1);
    }
    if (wid == 0) TCGEN05_ALLOC(sbase + SM_TMEM, 512);
    __syncthreads();
    uint32_t tmem;
    asm volatile("ld.shared.b32 %0, [%1];" : "=r"(tmem) : "r"(sbase + SM_TMEM));

    if (wid == 0) {
        // -------- MMA consumer warp --------
        TCGEN05_RELINQUISH();
        for (int c = 0; c < NCHUNK; c++) {
            const int s = c % NSTAGE;
            const int par = (c / NSTAGE) & 1;
            MBARRIER_WAIT_PARITY(sbase + SM_FULL0 + 8 * s, par);
            FENCE_PROXY_ASYNC();
            if (elect1()) {
                const uint32_t aA = sbase + SM_STAGE + s * STAGE_BYTES + SM_A_OFF;
                const uint32_t aB = aA + SM_B_OFF;
                const uint64_t da0 = make_desc_sw128(aA);
                const uint64_t da1 = make_desc_sw128(aA + 128 * 128); // rows 128..255
                const uint64_t db  = make_desc_sw128(aB);
#pragma unroll
                for (int kk = 0; kk < 4; kk++) {
                    const uint32_t en = (c == 0 && kk == 0) ? 0u : 1u;
                    mma_f16_ss(tmem + 0,   da0 + kk * 2, db + kk * 2, en);
                    mma_f16_ss(tmem + 256, da1 + kk * 2, db + kk * 2, en);
                }
                TCGEN05_COMMIT(sbase + SM_EMPTY0 + 8 * s);
            }
        }
        if (elect1()) TCGEN05_COMMIT(sbase + SM_DONE);
    } else if (wid <= 4) {
        // -------- cp.async producers (128 threads) --------
        const int pid = tid - 32;                 // 0..127
        const int r0 = pid >> 3;                  // base row 0..15
        const int c0 = (pid & 7) * 16;            // byte col within 128B row
        const char* gA = (const char*)Ain + (size_t)(m0 + r0) * (K3 * 2) + c0;
        const char* gB = (const char*)Bp  + (size_t)(n0 + r0) * (K3 * 2) + c0;
        for (int c = 0; c < NCHUNK; c++) {
            const int s = c % NSTAGE;
            const int par = ((c / NSTAGE) & 1) ^ 1;
            MBARRIER_WAIT_PARITY(sbase + SM_EMPTY0 + 8 * s, par);
            const uint32_t sA = sbase + SM_STAGE + s * STAGE_BYTES + SM_A_OFF;
            const uint32_t sB = sA + SM_B_OFF;
            const size_t koff = (size_t)c * 128;  // byte offset along K
#pragma unroll
            for (int u = 0; u < 16; u++) {
                const uint32_t so = swz128((u * 16 + r0) * 128 + c0);
                cp16(sA + so, gA + (size_t)u * 16 * (K3 * 2) + koff);
            }
#pragma unroll
            for (int u = 0; u < 16; u++) {
                const uint32_t so = swz128((u * 16 + r0) * 128 + c0);
                cp16(sB + so, gB + (size_t)u * 16 * (K3 * 2) + koff);
            }
            cp_arrive(sbase + SM_FULL0 + 8 * s);
        }
    }

    // -------- fused epilogue (all 256 threads) --------
    MBARRIER_WAIT_PARITY(sbase + SM_DONE, 0);
    TCGEN05_FENCE_AFTER();

    const int half = wid >> 2;                 // which 128-row MMA result
    const int m = m0 + half * 128 + (wid & 3) * 32 + lid;
    const float xb = use_x ? pred[m] : 0.0f;
    const uint32_t dbase = tmem + half * 256;
    const size_t mrow = (size_t)m * HDIM;
    const size_t arow = (size_t)m * K3;
    float psum = 0.0f;

#pragma unroll 1
    for (int nc = 0; nc < 8; nc++) {
        uint32_t r[32];
        TCGEN05_LD_X32(r, dbase + nc * 32);
        TCGEN05_WAIT_LD();
        const int nb = n0 + nc * 32;
        const int jb = j0 + nc * 8;
        const float4 ca = *(const float4*)(cbuf + mrow + jb);
        const float4 cb2 = *(const float4*)(cbuf + mrow + jb + 4);
        float cold[8] = {ca.x, ca.y, ca.z, ca.w, cb2.x, cb2.y, cb2.z, cb2.w};
        float cn[8];
        union { __nv_bfloat16 b[8]; uint4 v; } Uhi, Ulo;
#pragma unroll
        for (int jl = 0; jl < 8; jl++) {
            const int nn = nb + jl * 4;
            float iv = __uint_as_float(r[jl * 4 + 0]) + biasp[nn + 0] + xb * wihp[nn + 0];
            float fv = __uint_as_float(r[jl * 4 + 1]) + biasp[nn + 1] + xb * wihp[nn + 1];
            float gv = __uint_as_float(r[jl * 4 + 2]) + biasp[nn + 2] + xb * wihp[nn + 2];
            float ov = __uint_as_float(r[jl * 4 + 3]) + biasp[nn + 3] + xb * wihp[nn + 3];
            const float si = __fdividef(1.0f, 1.0f + __expf(-iv));
            const float sf = __fdividef(1.0f, 1.0f + __expf(-fv));
            const float so = __fdividef(1.0f, 1.0f + __expf(-ov));
            const float tg = 1.0f - __fdividef(2.0f, __expf(2.0f * gv) + 1.0f);
            const float c2 = sf * cold[jl] + si * tg;
            const float tc = 1.0f - __fdividef(2.0f, __expf(2.0f * c2) + 1.0f);
            const float hn = so * tc;
            cn[jl] = c2;
            const __nv_bfloat16 hi = __float2bfloat16_rn(hn);
            Uhi.b[jl] = hi;
            Ulo.b[jl] = __float2bfloat16_rn(hn - __bfloat162float(hi));
            psum = fmaf(hn, woutp[jb + jl], psum);
        }
        *(float4*)(cbuf + mrow + jb)     = make_float4(cn[0], cn[1], cn[2], cn[3]);
        *(float4*)(cbuf + mrow + jb + 4) = make_float4(cn[4], cn[5], cn[6], cn[7]);
        *(uint4*)(Aout + arow + jb)        = Uhi.v;   // h_hi
        *(uint4*)(Aout + arow + 2048 + jb) = Uhi.v;   // h_hi (dup for 3rd term)
        *(uint4*)(Aout + arow + 1024 + jb) = Ulo.v;   // h_lo
    }
    partial[(size_t)m * JT + blockIdx.y] = psum;

    __syncthreads();
    if (wid == 0) TCGEN05_DEALLOC(tmem, 512);
#endif  // HAS_TCGEN05  (non-'a' PTX pass compiles an empty stub; never executed)
}

// ---------------- pred reduce ----------------
__global__ void pred_reduce(const float* __restrict__ partial, const float* __restrict__ b_out,
                            float* __restrict__ pred, float* __restrict__ out, int t)
{
    const int b = blockIdx.x * blockDim.x + threadIdx.x;
    if (b < BSZ) {
        float s = b_out[0];
        const float* p = partial + (size_t)b * JT;
#pragma unroll
        for (int i = 0; i < JT; i++) s += p[i];
        pred[b] = s;
        out[(size_t)b * TLEN + t] = s;
    }
}

// ---------------- launch ----------------
extern "C" void kernel_launch(void* const* d_in, const int* in_sizes, int n_in,
                              void* d_out, int out_size)
{
    const float* hidden = (const float*)d_in[0];
    const float* cell   = (const float*)d_in[1];
    const float* W_ih   = (const float*)d_in[2];
    const float* W_hh   = (const float*)d_in[3];
    const float* b_ih   = (const float*)d_in[4];
    const float* b_hh   = (const float*)d_in[5];
    const float* W_out  = (const float*)d_in[6];
    const float* b_out  = (const float*)d_in[7];
    float* out = (float*)d_out;

    __nv_bfloat16 *Abuf, *Bp;
    float *cbuf, *biasp, *wihp, *woutp, *part, *pred;
    cudaGetSymbolAddress((void**)&Abuf,  g_A);
    cudaGetSymbolAddress((void**)&Bp,    g_Bp);
    cudaGetSymbolAddress((void**)&cbuf,  g_c);
    cudaGetSymbolAddress((void**)&biasp, g_biasp);
    cudaGetSymbolAddress((void**)&wihp,  g_wihp);
    cudaGetSymbolAddress((void**)&woutp, g_woutp);
    cudaGetSymbolAddress((void**)&part,  g_partial);
    cudaGetSymbolAddress((void**)&pred,  g_pred);

    cudaFuncSetAttribute(lstm_step_mma, cudaFuncAttributeMaxDynamicSharedMemorySize, DSMEM);

    prep_weights<<<(NGATE * HDIM + 255) / 256, 256>>>(W_ih, W_hh, b_ih, b_hh, W_out,
                                                      Bp, biasp, wihp, woutp);
    prep_state<<<(BSZ * HDIM + 255) / 256, 256>>>(hidden, cell, Abuf, cbuf);

    const size_t NA = (size_t)BSZ * K3;
    dim3 grid(BSZ / MT, NGATE / NT);
    for (int t = 0; t < TLEN; t++) {
        const __nv_bfloat16* Ain = Abuf + (size_t)(t & 1) * NA;
        __nv_bfloat16* Aout = Abuf + (size_t)((t + 1) & 1) * NA;
        lstm_step_mma<<<grid, 256, DSMEM>>>(Ain, Aout, Bp, cbuf, biasp, wihp, woutp,
                                            pred, (t > 0) ? 1 : 0, part);
        pred_reduce<<<BSZ / 256, 256>>>(part, b_out, pred, out, t);
    }
}

// round 4
// speedup vs baseline: 12.7987x; 1.1168x over previous
#include <cuda_runtime.h>
#include <cuda_bf16.h>
#include <math.h>
#include <stdint.h>

// ---------------- problem constants ----------------
#define HDIM  1024
#define BSZ   4096
#define TLEN  128
#define K2    2048            // stored K: [h_hi | h_lo] / [W_hi | W_lo]
#define NGATE 4096            // 4 gates x HDIM, interleaved n' = j*4 + g
#define MT    256
#define NT    256
#define KC    32              // K chunk (elems of original K=1024) = 64B rows, SW64
#define NCHUNK (HDIM/KC)      // 32
#define NSTAGE 3
#define JT    16

#if defined(__CUDA_ARCH__) && (defined(__CUDA_ARCH_FEAT_SM103_ALL) || defined(__CUDA_ARCH_FEAT_SM100_ALL) || defined(__CUDA_ARCH_FEAT_SM101_ALL))
#define HAS_TCGEN05 1
#else
#define HAS_TCGEN05 0
#endif

// ---------------- persistent device state ----------------
__device__ __nv_bfloat16 g_A[2][(size_t)BSZ * K2];     // activations [h_hi|h_lo] (ping-pong)
__device__ __nv_bfloat16 g_Bp[(size_t)NGATE * K2];     // weights [W_hi|W_lo], gate-interleaved
__device__ float g_c[(size_t)BSZ * HDIM];
__device__ float g_biasp[NGATE];
__device__ float g_wihp[NGATE];
__device__ float g_woutp[HDIM];
__device__ float g_partial[2][(size_t)BSZ * JT];       // double-buffered (race-free fusion)

// ---------------- smem layout ----------------
#define SM_TMEM   0
#define SM_FULL0  64
#define SM_EMPTY0 (SM_FULL0 + 8*NSTAGE)
#define SM_DONE   (SM_EMPTY0 + 8*NSTAGE)
#define SM_STAGE  1024
#define STAGE_BYTES 65536       // A_hi 16K | A_lo 16K | B_hi 16K | B_lo 16K
#define OFF_AHI 0
#define OFF_ALO 16384
#define OFF_BHI 32768
#define OFF_BLO 49152
#define DSMEM (SM_STAGE + NSTAGE*STAGE_BYTES)
#define N_PROD_THREADS 128

// idesc: F32 accum, BF16 a/b, N=256, M=128
#define MMA_IDESC 0x08400490u

// ---------------- arch-neutral helpers ----------------
__device__ __forceinline__ uint32_t smem_u32(const void* p) {
    uint32_t a;
    asm("{ .reg .u64 t; cvta.to.shared.u64 t, %1; cvt.u32.u64 %0, t; }" : "=r"(a) : "l"(p));
    return a;
}
__device__ __forceinline__ uint32_t elect1() {
    uint32_t r;
    asm volatile("{ .reg .pred p; elect.sync _|p, 0xFFFFFFFF; selp.b32 %0, 1, 0, p; }" : "=r"(r));
    return r;
}
#define MBARRIER_INIT(addr, cnt) \
    asm volatile("mbarrier.init.shared.b64 [%0], %1;" :: "r"((uint32_t)(addr)), "r"((uint32_t)(cnt)) : "memory")
#define MBARRIER_WAIT_PARITY(addr, par) do { \
    uint32_t _m = (uint32_t)(addr); uint32_t _p = (uint32_t)(par); uint32_t _d; \
    asm volatile("{ .reg .pred p; mbarrier.try_wait.parity.acquire.cta.shared::cta.b64 p, [%1], %2; selp.b32 %0,1,0,p; }" \
        : "=r"(_d) : "r"(_m), "r"(_p) : "memory"); \
    if (!_d) { \
        asm volatile("{ .reg .pred P1; WL_%=: mbarrier.try_wait.parity.acquire.cta.shared::cta.b64 P1, [%0], %1, 0x989680; @P1 bra.uni WD_%=; bra.uni WL_%=; WD_%=: }" \
            :: "r"(_m), "r"(_p) : "memory"); \
    } } while (0)
__device__ __forceinline__ void cp16(uint32_t saddr, const void* gaddr) {
    asm volatile("cp.async.cg.shared.global [%0], [%1], 16;" :: "r"(saddr), "l"(gaddr));
}
__device__ __forceinline__ void cp_arrive(uint32_t mbar) {
    asm volatile("cp.async.mbarrier.arrive.noinc.shared::cta.b64 [%0];" :: "r"(mbar) : "memory");
}
__device__ __forceinline__ uint32_t swz64(uint32_t o) { return o ^ ((o >> 3) & 0x30); }

// SW64 K-major smem descriptor: layout 4, version 1, SBO=32 (512B atom stride), LBO=1
static __device__ __forceinline__ uint64_t make_desc_sw64(uint32_t addr) {
    const uint64_t base = (uint64_t(4) << 61) | (uint64_t(1) << 46) | (uint64_t(32) << 32) | (uint64_t(1) << 16);
    return base | ((uint64_t)(addr >> 4) & 0x3FFF);
}

// ---------------- tcgen05 (sm_103a-only PTX pass) ----------------
#if HAS_TCGEN05
#define TCGEN05_ALLOC(sa, n) \
    asm volatile("tcgen05.alloc.cta_group::1.sync.aligned.shared::cta.b32 [%0], %1;" :: "r"((uint32_t)(sa)), "r"((uint32_t)(n)) : "memory")
#define TCGEN05_DEALLOC(t, n) \
    asm volatile("tcgen05.dealloc.cta_group::1.sync.aligned.b32 %0, %1;" :: "r"(t), "r"((uint32_t)(n)))
#define TCGEN05_RELINQUISH() \
    asm volatile("tcgen05.relinquish_alloc_permit.cta_group::1.sync.aligned;")
#define TCGEN05_COMMIT(mb) \
    asm volatile("tcgen05.commit.cta_group::1.mbarrier::arrive::one.shared::cluster.b64 [%0];" :: "r"((uint32_t)(mb)) : "memory")
#define TCGEN05_FENCE_AFTER()  asm volatile("tcgen05.fence::after_thread_sync;" ::: "memory")
#define TCGEN05_WAIT_LD()      asm volatile("tcgen05.wait::ld.sync.aligned;" ::: "memory")
#define FENCE_PROXY_ASYNC()    asm volatile("fence.proxy.async.shared::cta;" ::: "memory")

#define TCGEN05_LD_X32(r, ta) \
    asm volatile("tcgen05.ld.sync.aligned.32x32b.x32.b32 " \
        "{%0,%1,%2,%3,%4,%5,%6,%7,%8,%9,%10,%11,%12,%13,%14,%15," \
        "%16,%17,%18,%19,%20,%21,%22,%23,%24,%25,%26,%27,%28,%29,%30,%31}, [%32];" \
        : "=r"((r)[0]),"=r"((r)[1]),"=r"((r)[2]),"=r"((r)[3]),"=r"((r)[4]),"=r"((r)[5]),"=r"((r)[6]),"=r"((r)[7]), \
          "=r"((r)[8]),"=r"((r)[9]),"=r"((r)[10]),"=r"((r)[11]),"=r"((r)[12]),"=r"((r)[13]),"=r"((r)[14]),"=r"((r)[15]), \
          "=r"((r)[16]),"=r"((r)[17]),"=r"((r)[18]),"=r"((r)[19]),"=r"((r)[20]),"=r"((r)[21]),"=r"((r)[22]),"=r"((r)[23]), \
          "=r"((r)[24]),"=r"((r)[25]),"=r"((r)[26]),"=r"((r)[27]),"=r"((r)[28]),"=r"((r)[29]),"=r"((r)[30]),"=r"((r)[31]) \
        : "r"(ta))

__device__ __forceinline__ void mma_f16_ss(uint32_t d, uint64_t ad, uint64_t bd, uint32_t en) {
    asm volatile(
        "{ .reg .pred p; setp.ne.u32 p, %4, 0;\n\t"
        "tcgen05.mma.cta_group::1.kind::f16 [%0], %1, %2, %3, {%5,%5,%5,%5}, p; }"
        :: "r"(d), "l"(ad), "l"(bd), "r"(MMA_IDESC), "r"(en), "r"(0u) : "memory");
}
#endif

// ---------------- prep kernels ----------------
__global__ void prep_weights(const float* __restrict__ W_ih, const float* __restrict__ W_hh,
                             const float* __restrict__ b_ih, const float* __restrict__ b_hh,
                             const float* __restrict__ W_out,
                             __nv_bfloat16* __restrict__ Bp, float* __restrict__ biasp,
                             float* __restrict__ wihp, float* __restrict__ woutp)
{
    int idx = blockIdx.x * blockDim.x + threadIdx.x;
    if (idx >= NGATE * HDIM) return;
    int np = idx / HDIM, k = idx - np * HDIM;
    int gg = np & 3, j = np >> 2;
    int src = gg * HDIM + j;
    float w = W_hh[(size_t)src * HDIM + k];
    __nv_bfloat16 hi = __float2bfloat16_rn(w);
    __nv_bfloat16 lo = __float2bfloat16_rn(w - __bfloat162float(hi));
    Bp[(size_t)np * K2 + k]        = hi;
    Bp[(size_t)np * K2 + 1024 + k] = lo;
    if (k == 0) { biasp[np] = b_ih[src] + b_hh[src]; wihp[np] = W_ih[src]; }
    if (np == 0) woutp[k] = W_out[k];
}

__global__ void prep_state(const float* __restrict__ hidden, const float* __restrict__ cell,
                           __nv_bfloat16* __restrict__ A0, float* __restrict__ cbuf)
{
    int idx = blockIdx.x * blockDim.x + threadIdx.x;
    if (idx >= BSZ * HDIM) return;
    int m = idx / HDIM, k = idx - m * HDIM;
    float h = hidden[idx];
    __nv_bfloat16 hi = __float2bfloat16_rn(h);
    __nv_bfloat16 lo = __float2bfloat16_rn(h - __bfloat162float(hi));
    A0[(size_t)m * K2 + k]        = hi;
    A0[(size_t)m * K2 + 1024 + k] = lo;
    cbuf[idx] = cell[idx];
}

// ---------------- fused LSTM step ----------------
// gates = W_hi·h_hi + W_hi·h_lo + W_lo·h_hi  (fp32 TMEM accum; dropped W_lo·h_lo ~2^-19)
__global__ void __launch_bounds__(256, 1)
lstm_step_mma(const __nv_bfloat16* __restrict__ Ain, __nv_bfloat16* __restrict__ Aout,
              const __nv_bfloat16* __restrict__ Bp, float* __restrict__ cbuf,
              const float* __restrict__ biasp, const float* __restrict__ wihp,
              const float* __restrict__ woutp,
              const float* __restrict__ partial_prev, float* __restrict__ partial,
              const float* __restrict__ b_out, float* __restrict__ out,
              int t, int use_x)
{
#if HAS_TCGEN05
    extern __shared__ char smem[];
    const uint32_t sbase = smem_u32(smem);
    const int tid = threadIdx.x, wid = tid >> 5, lid = tid & 31;
    const int m0 = blockIdx.x * MT, n0 = blockIdx.y * NT, j0 = n0 >> 2;

    if (tid == 0) {
#pragma unroll
        for (int s = 0; s < NSTAGE; s++) {
            MBARRIER_INIT(sbase + SM_FULL0 + 8 * s, N_PROD_THREADS);
            MBARRIER_INIT(sbase + SM_EMPTY0 + 8 * s, 1);
        }
        MBARRIER_INIT(sbase + SM_DONE, 1);
    }
    if (wid == 0) TCGEN05_ALLOC(sbase + SM_TMEM, 512);
    __syncthreads();
    uint32_t tmem;
    asm volatile("ld.shared.b32 %0, [%1];" : "=r"(tmem) : "r"(sbase + SM_TMEM));

    if (wid == 0) {
        // -------- MMA warp: 3 cross-products from resident tiles --------
        TCGEN05_RELINQUISH();
        for (int c = 0; c < NCHUNK; c++) {
            const int s = c % NSTAGE;
            const int par = (c / NSTAGE) & 1;
            MBARRIER_WAIT_PARITY(sbase + SM_FULL0 + 8 * s, par);
            FENCE_PROXY_ASYNC();
            if (elect1()) {
                const uint32_t aT = sbase + SM_STAGE + s * STAGE_BYTES;
                const uint64_t dAhi = make_desc_sw64(aT + OFF_AHI);
                const uint64_t dAlo = make_desc_sw64(aT + OFF_ALO);
                const uint64_t dBhi = make_desc_sw64(aT + OFF_BHI);
                const uint64_t dBlo = make_desc_sw64(aT + OFF_BLO);
                // m-half offset: 128 rows * 64B = 8192B = 512 desc units
#pragma unroll
                for (int kk = 0; kk < 2; kk++) {
                    const uint32_t en0 = (c == 0 && kk == 0) ? 0u : 1u;
                    mma_f16_ss(tmem + 0,   dAhi + kk * 2,       dBhi + kk * 2, en0);
                    mma_f16_ss(tmem + 256, dAhi + 512 + kk * 2, dBhi + kk * 2, en0);
                    mma_f16_ss(tmem + 0,   dAlo + kk * 2,       dBhi + kk * 2, 1u);
                    mma_f16_ss(tmem + 256, dAlo + 512 + kk * 2, dBhi + kk * 2, 1u);
                    mma_f16_ss(tmem + 0,   dAhi + kk * 2,       dBlo + kk * 2, 1u);
                    mma_f16_ss(tmem + 256, dAhi + 512 + kk * 2, dBlo + kk * 2, 1u);
                }
                TCGEN05_COMMIT(sbase + SM_EMPTY0 + 8 * s);
            }
        }
        if (elect1()) TCGEN05_COMMIT(sbase + SM_DONE);
    } else if (wid <= 4) {
        // -------- producers: 4 tiles x 16KB per chunk --------
        const int pid = tid - 32;             // 0..127
        const int r0 = pid >> 2;              // 0..31
        const int c16 = pid & 3;              // 16B column within 64B row
        const char* gAh = (const char*)Ain + (size_t)(m0 + r0) * (K2 * 2) + c16 * 16;
        const char* gAl = gAh + 2048;         // +1024 bf16 elems
        const char* gBh = (const char*)Bp + (size_t)(n0 + r0) * (K2 * 2) + c16 * 16;
        const char* gBl = gBh + 2048;
        uint32_t so[8];
#pragma unroll
        for (int u = 0; u < 8; u++) so[u] = swz64((r0 + 32 * u) * 64 + c16 * 16);

        for (int c = 0; c < NCHUNK; c++) {
            const int s = c % NSTAGE;
            const int par = ((c / NSTAGE) & 1) ^ 1;
            MBARRIER_WAIT_PARITY(sbase + SM_EMPTY0 + 8 * s, par);
            const uint32_t sT = sbase + SM_STAGE + s * STAGE_BYTES;
            const size_t koff = (size_t)c * 64;      // 32 elems = 64B along K
#pragma unroll
            for (int u = 0; u < 8; u++) {
                const size_t grow = (size_t)u * 32 * (K2 * 2);
                cp16(sT + OFF_AHI + so[u], gAh + grow + koff);
                cp16(sT + OFF_ALO + so[u], gAl + grow + koff);
                cp16(sT + OFF_BHI + so[u], gBh + grow + koff);
                cp16(sT + OFF_BLO + so[u], gBl + grow + koff);
            }
            cp_arrive(sbase + SM_FULL0 + 8 * s);
        }
    }

    // -------- fused epilogue --------
    MBARRIER_WAIT_PARITY(sbase + SM_DONE, 0);
    TCGEN05_FENCE_AFTER();

    const int half = wid >> 2;
    const int m = m0 + half * 128 + (wid & 3) * 32 + lid;

    // fused pred-reduce of PREVIOUS step (replaces the pred_reduce kernel)
    float xb = 0.0f;
    if (use_x) {
        const float4* pp = (const float4*)(partial_prev + (size_t)m * JT);
        float4 p0 = pp[0], p1 = pp[1], p2 = pp[2], p3 = pp[3];
        float s = b_out[0];
        s += p0.x + p0.y + p0.z + p0.w;
        s += p1.x + p1.y + p1.z + p1.w;
        s += p2.x + p2.y + p2.z + p2.w;
        s += p3.x + p3.y + p3.z + p3.w;
        xb = s;
        if (blockIdx.y == 0) out[(size_t)m * TLEN + (t - 1)] = s;
    }

    const uint32_t dbase = tmem + half * 256;
    const size_t mrow = (size_t)m * HDIM;
    const size_t arow = (size_t)m * K2;
    float psum = 0.0f;

#pragma unroll 1
    for (int nc = 0; nc < 8; nc++) {
        uint32_t r[32];
        TCGEN05_LD_X32(r, dbase + nc * 32);
        TCGEN05_WAIT_LD();
        const int nb = n0 + nc * 32;
        const int jb = j0 + nc * 8;
        const float4 ca = *(const float4*)(cbuf + mrow + jb);
        const float4 cb2 = *(const float4*)(cbuf + mrow + jb + 4);
        float cold[8] = {ca.x, ca.y, ca.z, ca.w, cb2.x, cb2.y, cb2.z, cb2.w};
        float cn[8];
        union { __nv_bfloat16 b[8]; uint4 v; } Uhi, Ulo;
#pragma unroll
        for (int jl = 0; jl < 8; jl++) {
            const int nn = nb + jl * 4;
            float iv = __uint_as_float(r[jl * 4 + 0]) + biasp[nn + 0] + xb * wihp[nn + 0];
            float fv = __uint_as_float(r[jl * 4 + 1]) + biasp[nn + 1] + xb * wihp[nn + 1];
            float gv = __uint_as_float(r[jl * 4 + 2]) + biasp[nn + 2] + xb * wihp[nn + 2];
            float ov = __uint_as_float(r[jl * 4 + 3]) + biasp[nn + 3] + xb * wihp[nn + 3];
            const float si = __fdividef(1.0f, 1.0f + __expf(-iv));
            const float sf = __fdividef(1.0f, 1.0f + __expf(-fv));
            const float so2 = __fdividef(1.0f, 1.0f + __expf(-ov));
            const float tg = 1.0f - __fdividef(2.0f, __expf(2.0f * gv) + 1.0f);
            const float c2 = sf * cold[jl] + si * tg;
            const float tc = 1.0f - __fdividef(2.0f, __expf(2.0f * c2) + 1.0f);
            const float hn = so2 * tc;
            cn[jl] = c2;
            const __nv_bfloat16 hi = __float2bfloat16_rn(hn);
            Uhi.b[jl] = hi;
            Ulo.b[jl] = __float2bfloat16_rn(hn - __bfloat162float(hi));
            psum = fmaf(hn, woutp[jb + jl], psum);
        }
        *(float4*)(cbuf + mrow + jb)     = make_float4(cn[0], cn[1], cn[2], cn[3]);
        *(float4*)(cbuf + mrow + jb + 4) = make_float4(cn[4], cn[5], cn[6], cn[7]);
        *(uint4*)(Aout + arow + jb)        = Uhi.v;   // h_hi
        *(uint4*)(Aout + arow + 1024 + jb) = Ulo.v;   // h_lo
    }
    partial[(size_t)m * JT + blockIdx.y] = psum;

    __syncthreads();
    if (wid == 0) TCGEN05_DEALLOC(tmem, 512);
#endif
}

// final column (t = TLEN-1) reduce
__global__ void pred_final(const float* __restrict__ partial, const float* __restrict__ b_out,
                           float* __restrict__ out)
{
    const int b = blockIdx.x * blockDim.x + threadIdx.x;
    if (b < BSZ) {
        float s = b_out[0];
        const float* p = partial + (size_t)b * JT;
#pragma unroll
        for (int i = 0; i < JT; i++) s += p[i];
        out[(size_t)b * TLEN + (TLEN - 1)] = s;
    }
}

// ---------------- launch ----------------
extern "C" void kernel_launch(void* const* d_in, const int* in_sizes, int n_in,
                              void* d_out, int out_size)
{
    const float* hidden = (const float*)d_in[0];
    const float* cell   = (const float*)d_in[1];
    const float* W_ih   = (const float*)d_in[2];
    const float* W_hh   = (const float*)d_in[3];
    const float* b_ih   = (const float*)d_in[4];
    const float* b_hh   = (const float*)d_in[5];
    const float* W_out  = (const float*)d_in[6];
    const float* b_out  = (const float*)d_in[7];
    float* out = (float*)d_out;

    __nv_bfloat16 *Abuf, *Bp;
    float *cbuf, *biasp, *wihp, *woutp, *part;
    cudaGetSymbolAddress((void**)&Abuf,  g_A);
    cudaGetSymbolAddress((void**)&Bp,    g_Bp);
    cudaGetSymbolAddress((void**)&cbuf,  g_c);
    cudaGetSymbolAddress((void**)&biasp, g_biasp);
    cudaGetSymbolAddress((void**)&wihp,  g_wihp);
    cudaGetSymbolAddress((void**)&woutp, g_woutp);
    cudaGetSymbolAddress((void**)&part,  g_partial);

    cudaFuncSetAttribute(lstm_step_mma, cudaFuncAttributeMaxDynamicSharedMemorySize, DSMEM);

    prep_weights<<<(NGATE * HDIM + 255) / 256, 256>>>(W_ih, W_hh, b_ih, b_hh, W_out,
                                                      Bp, biasp, wihp, woutp);
    prep_state<<<(BSZ * HDIM + 255) / 256, 256>>>(hidden, cell, Abuf, cbuf);

    const size_t NA = (size_t)BSZ * K2;
    const size_t NP = (size_t)BSZ * JT;
    dim3 grid(BSZ / MT, NGATE / NT);
    for (int t = 0; t < TLEN; t++) {
        const __nv_bfloat16* Ain = Abuf + (size_t)(t & 1) * NA;
        __nv_bfloat16* Aout = Abuf + (size_t)((t + 1) & 1) * NA;
        const float* ppart = part + (size_t)((t + 1) & 1) * NP;  // (t-1)&1 == (t+1)&1
        float* cpart = part + (size_t)(t & 1) * NP;
        lstm_step_mma<<<grid, 256, DSMEM>>>(Ain, Aout, Bp, cbuf, biasp, wihp, woutp,
                                            ppart, cpart, b_out, out, t, (t > 0) ? 1 : 0);
    }
    pred_final<<<BSZ / 256, 256>>>(part + (size_t)((TLEN - 1) & 1) * NP, b_out, out);
}